// round 14
// baseline (speedup 1.0000x reference)
#include <cuda_runtime.h>
#include <cuda_bf16.h>
#include <cstdint>

// Persistent LSTM: B=128, T=365, D=32, H=512, fp32 I/O, out[b,t,:]=h_t.
// 128 CTAs x 512 threads (16 warps). CTA tile 32 batch(m) x 16 units x 4
// gates (n=64, n = u_local*4 + gate). Warp tile m16 x n8 -> 2 m-tiles x 8
// n-tiles. GEMM: mma.sync m16n8k16 bf16, fp32 accum, 3-MMA hi/lo split.
// W resident in smem [n][k] bf16 hi/lo planes (pitch 1104B). A (h|x) in smem
// [k][hi32|lo32] rows (pitch 144B), staged per step via cp.async from g_h
// (h published as bf16 hi/lo) and g_x (prologue-transposed x).
// R14: single producer counter polled by ALL threads (no second poll, one
// less sync); pipelined commit groups X/A/B with x-chunk-first compute.

#define B_   128
#define T_   365
#define D_   32
#define H_   512
#define G4   2048
#define KTOT 544
#define NCTA 128
#define NTHR 512

#define SWP   1104                    // W row pitch bytes
#define SWLO  (64 * SWP)              // lo-plane offset
#define SW_BYTES (128 * SWP)          // 141312
#define SAP   144                     // A row pitch bytes
#define SA_BYTES (KTOT * SAP)         // 78336
#define SMEM_BYTES (SW_BYTES + SA_BYTES)   // 219648

__device__ unsigned char g_h[2][4][512][128];   // [parity][mb][unit][hi|lo bf16]
__device__ unsigned char g_x[4][T_][32][128];   // [mb][t][d][hi|lo bf16]
__device__ unsigned int g_cnt[4];               // producers arrived (x32/step)
__device__ unsigned int g_init[4];

__global__ void init_ctrl_kernel() {
    if (threadIdx.x < 4) { g_cnt[threadIdx.x] = 0u; g_init[threadIdx.x] = 0u; }
}

__device__ __forceinline__ float fsig(float z) {
    return 1.0f / (1.0f + __expf(-z));
}
__device__ __forceinline__ float ftanh_(float z) {
    return 1.0f - 2.0f / (__expf(2.0f * z) + 1.0f);
}
__device__ __forceinline__ void cp_async16(unsigned int smem_dst, const void* gsrc) {
    asm volatile("cp.async.cg.shared.global [%0], [%1], 16;"
                 :: "r"(smem_dst), "l"(gsrc) : "memory");
}
#define CP_COMMIT() asm volatile("cp.async.commit_group;" ::: "memory")
#define CP_WAIT(N)  asm volatile("cp.async.wait_group %0;" :: "n"(N) : "memory")
__device__ __forceinline__ unsigned int smem_u32(const void* p) {
    return (unsigned int)__cvta_generic_to_shared(p);
}
__device__ __forceinline__ unsigned int ld_acq(const unsigned int* p) {
    unsigned int v;
    asm volatile("ld.acquire.gpu.global.u32 %0, [%1];" : "=r"(v) : "l"(p));
    return v;
}
__device__ __forceinline__ void ldsm4t(uint32_t& r0, uint32_t& r1, uint32_t& r2,
                                       uint32_t& r3, uint32_t a) {
    asm volatile("ldmatrix.sync.aligned.m8n8.x4.trans.shared.b16 {%0,%1,%2,%3}, [%4];"
                 : "=r"(r0), "=r"(r1), "=r"(r2), "=r"(r3) : "r"(a));
}
__device__ __forceinline__ void ldsm2(uint32_t& r0, uint32_t& r1, uint32_t a) {
    asm volatile("ldmatrix.sync.aligned.m8n8.x2.shared.b16 {%0,%1}, [%2];"
                 : "=r"(r0), "=r"(r1) : "r"(a));
}
__device__ __forceinline__ void mma16816(float* c,
                                         uint32_t a0, uint32_t a1, uint32_t a2,
                                         uint32_t a3, uint32_t b0, uint32_t b1) {
    asm volatile(
        "mma.sync.aligned.m16n8k16.row.col.f32.bf16.bf16.f32 "
        "{%0,%1,%2,%3}, {%4,%5,%6,%7}, {%8,%9}, {%0,%1,%2,%3};"
        : "+f"(c[0]), "+f"(c[1]), "+f"(c[2]), "+f"(c[3])
        : "r"(a0), "r"(a1), "r"(a2), "r"(a3), "r"(b0), "r"(b1));
}
__device__ __forceinline__ void store_h_bf(unsigned char* row, int mloc, float h) {
    __nv_bfloat16 hi = __float2bfloat16(h);
    float lo = h - __bfloat162float(hi);
    *(__nv_bfloat16*)(row + mloc * 2) = hi;
    *(__nv_bfloat16*)(row + 64 + mloc * 2) = __float2bfloat16(lo);
}

// One k16 iteration for warp tile m16 x n8: 2 ldsm.x4 (A hi/lo, trans) +
// 2 ldsm.x2 (B hi/lo) + 3 MMA (hi*hi, hi*lo, lo*hi).
#define MMAIT(K0) do {                                                        \
    uint32_t ah0,ah1,ah2,ah3, al0,al1,al2,al3;                                \
    uint32_t bh0,bh1, bl0,bl1;                                                \
    ldsm4t(ah0,ah1,ah2,ah3, aHi + (unsigned)(K0) * SAP);                      \
    ldsm4t(al0,al1,al2,al3, aHi + (unsigned)(K0) * SAP + 64u);                \
    ldsm2 (bh0,bh1, bAd + (unsigned)(K0) * 2u);                               \
    ldsm2 (bl0,bl1, bAd + (unsigned)(K0) * 2u + SWLO);                        \
    mma16816(acc, ah0,ah1,ah2,ah3, bh0,bh1);                                  \
    mma16816(acc, ah0,ah1,ah2,ah3, bl0,bl1);                                  \
    mma16816(acc, al0,al1,al2,al3, bh0,bh1);                                  \
} while (0)

__global__ __launch_bounds__(NTHR, 1) void lstm_persistent(
    const float* __restrict__ x,    // [B,T,D]
    const float* __restrict__ Wx,   // [D,4H]
    const float* __restrict__ Wh,   // [H,4H]
    const float* __restrict__ bias, // [4H]
    float* __restrict__ out)        // [B,T,H]
{
    extern __shared__ char smem[];
    char* sA = smem + SW_BYTES;
    const unsigned int sWu = smem_u32(smem);
    const unsigned int sAu = smem_u32(sA);

    const int tid  = threadIdx.x;
    const int warp = tid >> 5;
    const int lane = tid & 31;
    const int mt   = warp & 1;               // m-tile (16 rows)
    const int nt   = warp >> 1;              // n-tile (8 gatecols = 2 units)
    const int ub   = blockIdx.x & 31;
    const int mb   = blockIdx.x >> 5;
    const int j0   = ub * 16;
    const int m0   = mb * 32;

    // ---- prologue: W -> bf16 hi/lo planes, [n][k], n = u*4+g ----
    for (int i = 0; i < (64 * KTOT) / NTHR; ++i) {   // 68 iters
        int idx = i * NTHR + tid;
        int n = idx & 63;
        int k = idx >> 6;
        int col = (n & 3) * H_ + j0 + (n >> 2);
        float w = (k < H_) ? Wh[(size_t)k * G4 + col]
                           : Wx[(size_t)(k - H_) * G4 + col];
        __nv_bfloat16 hi = __float2bfloat16(w);
        float lo = w - __bfloat162float(hi);
        *(__nv_bfloat16*)(smem + n * SWP + k * 2) = hi;
        *(__nv_bfloat16*)(smem + SWLO + n * SWP + k * 2) = __float2bfloat16(lo);
    }

    // ---- prologue: transpose+convert x share into g_x ----
    {
        float* sX = (float*)sA;                      // scratch [32][33]
        for (int tt = ub; tt < T_; tt += 32) {
            float v[2];
            #pragma unroll
            for (int i = 0; i < 2; ++i) {
                int e = i * NTHR + tid;
                int m = e >> 5, d = e & 31;
                v[i] = x[(size_t)(m0 + m) * (T_ * D_) + (size_t)tt * D_ + d];
            }
            __syncthreads();
            #pragma unroll
            for (int i = 0; i < 2; ++i) {
                int e = i * NTHR + tid;
                int m = e >> 5, d = e & 31;
                sX[d * 33 + m] = v[i];
            }
            __syncthreads();
            unsigned char* gx = &g_x[mb][tt][0][0];
            #pragma unroll
            for (int i = 0; i < 2; ++i) {
                int e = i * NTHR + tid;
                int d = e >> 5, m = e & 31;
                float val = sX[d * 33 + m];
                __nv_bfloat16 hi = __float2bfloat16(val);
                float lo = val - __bfloat162float(hi);
                *(__nv_bfloat16*)(gx + d * 128 + m * 2) = hi;
                *(__nv_bfloat16*)(gx + d * 128 + 64 + m * 2) = __float2bfloat16(lo);
            }
            __syncthreads();
        }
    }

    // ---- zero A region; cross-CTA barrier for g_x; stage x(0) ----
    for (int i = tid; i < SA_BYTES / 4; i += NTHR) ((float*)sA)[i] = 0.f;
    __threadfence();
    __syncthreads();
    if (tid == 0) {
        atomicAdd(&g_init[mb], 1u);
        while (ld_acq(&g_init[mb]) < 32u) { }
    }
    __syncthreads();
    if (tid < 256)
        cp_async16(sAu + (unsigned)(512 + (tid >> 3)) * SAP + (tid & 7) * 16,
                   &g_x[mb][0][0][0] + (tid >> 3) * 128 + (tid & 7) * 16);
    CP_COMMIT(); CP_WAIT(0);
    __syncthreads();

    // ---- per-lane fragment addresses ----
    const int li = lane & 7;
    const unsigned int aHi = sAu
        + (unsigned)((((lane >> 4) & 1) * 8 + li) * SAP)
        + (unsigned)((mt * 16 + ((lane >> 3) & 1) * 8) * 2);
    const unsigned int bAd = sWu
        + (unsigned)((nt * 8 + li) * SWP)
        + (unsigned)(((lane >> 3) & 1) * 16);

    // ---- epilogue constants ----
    // c-frag: c0/c1 = row (lane>>2), cols 2*(lane&3), +1; c2/c3 = row+8.
    // (lane&3) even -> own cols = gates (i,f); odd -> (g,o). Pair via xor(1).
    const bool acting = ((lane & 1) == 0);
    const int j = j0 + nt * 2 + ((lane & 3) >> 1);
    const float bI = bias[j],          bF = bias[H_ + j];
    const float bG = bias[2 * H_ + j], bO = bias[3 * H_ + j];
    float cS[2] = {0.f, 0.f};

    for (int t = 0; t < T_; ++t) {
        float acc[4] = {0.f, 0.f, 0.f, 0.f};

        if (t > 0) {
            // single poll by ALL threads (counter hits 32*t when every
            // producer of this mb published h(t-1))
            unsigned tgt = 32u * (unsigned)t;
            while (ld_acq(&g_cnt[mb]) < tgt) { }

            const unsigned char* hsrc = &g_h[(t - 1) & 1][mb][0][0];
            const unsigned char* xsrc = &g_x[mb][t][0][0];
            // group X: x(t), 4KB
            if (tid < 256)
                cp_async16(sAu + (unsigned)(512 + (tid >> 3)) * SAP + (tid & 7) * 16,
                           xsrc + (tid >> 3) * 128 + (tid & 7) * 16);
            CP_COMMIT();
            // group A: h rows [0,256)
            #pragma unroll
            for (int i = 0; i < 4; ++i) {
                int g = i * NTHR + tid;
                int row = g >> 3, c = g & 7;
                cp_async16(sAu + (unsigned)row * SAP + c * 16,
                           hsrc + row * 128 + c * 16);
            }
            CP_COMMIT();
            // group B: h rows [256,512)
            #pragma unroll
            for (int i = 0; i < 4; ++i) {
                int g = 2048 + i * NTHR + tid;
                int row = g >> 3, c = g & 7;
                cp_async16(sAu + (unsigned)row * SAP + c * 16,
                           hsrc + row * 128 + c * 16);
            }
            CP_COMMIT();
            CP_WAIT(2);                      // X landed
            __syncthreads();
        }

        // x chunk first (h-independent; covers group A flight)
        MMAIT(512); MMAIT(528);

        if (t > 0) { CP_WAIT(1); __syncthreads(); }
        #pragma unroll 2
        for (int k0 = 0; k0 < 256; k0 += 16) MMAIT(k0);

        if (t > 0) { CP_WAIT(0); __syncthreads(); }
        #pragma unroll 2
        for (int k0 = 256; k0 < 512; k0 += 16) MMAIT(k0);

        // ---- epilogue: pair (i,f) with partner's (g,o) via shfl.xor(1) ----
        float s0 = __shfl_xor_sync(0xffffffffu, acc[0], 1);
        float s1 = __shfl_xor_sync(0xffffffffu, acc[1], 1);
        float s2 = __shfl_xor_sync(0xffffffffu, acc[2], 1);
        float s3 = __shfl_xor_sync(0xffffffffu, acc[3], 1);

        if (acting) {
            const int r    = lane >> 2;
            const int mloc = mt * 16 + r;
            unsigned char* gh = &g_h[t & 1][mb][j][0];
            float* o0 = out + (size_t)(m0 + mloc) * ((size_t)T_ * H_) + (size_t)t * H_;
            float* o1 = out + (size_t)(m0 + mloc + 8) * ((size_t)T_ * H_) + (size_t)t * H_;
            {   // row mloc
                float ig = fsig(acc[0] + bI), fg = fsig(acc[1] + bF);
                float gg = ftanh_(s0 + bG),   og = fsig(s1 + bO);
                cS[0] = fg * cS[0] + ig * gg;
                float h = og * ftanh_(cS[0]);
                o0[j] = h; store_h_bf(gh, mloc, h);
            }
            {   // row mloc+8
                float ig = fsig(acc[2] + bI), fg = fsig(acc[3] + bF);
                float gg = ftanh_(s2 + bG),   og = fsig(s3 + bO);
                cS[1] = fg * cS[1] + ig * gg;
                float h = og * ftanh_(cS[1]);
                o1[j] = h; store_h_bf(gh, mloc + 8, h);
            }
        }
        __syncthreads();
        if (tid == 0) {
            __threadfence();
            atomicAdd(&g_cnt[mb], 1u);
        }
    }
}

extern "C" void kernel_launch(void* const* d_in, const int* in_sizes, int n_in,
                              void* d_out, int out_size) {
    const float* x  = (const float*)d_in[0];
    const float* Wx = (const float*)d_in[1];
    const float* Wh = (const float*)d_in[2];
    const float* b  = (const float*)d_in[3];
    float* out = (float*)d_out;

    static bool attr_set = false;
    if (!attr_set) {
        cudaFuncSetAttribute(lstm_persistent,
                             cudaFuncAttributeMaxDynamicSharedMemorySize,
                             SMEM_BYTES);
        attr_set = true;
    }

    init_ctrl_kernel<<<1, 32>>>();
    lstm_persistent<<<NCTA, NTHR, SMEM_BYTES>>>(x, Wx, Wh, b, out);
}